// round 7
// baseline (speedup 1.0000x reference)
#include <cuda_runtime.h>
#include <cuda_fp16.h>

#define N_NODES 65536
#define N_EDGES 1048576
#define HID 80
#define NPB 16   // nodes per k_node block
#define VPN 24   // uint4 (channel-pairs) per node

// ---------------- static scratch (no allocations allowed) ----------------
__device__ __half2 g_hh[N_NODES * 40];       // h as fp16: 40 half2/node (10.5 MB)
__device__ uint4   g_V[N_NODES * VPN];       // 2 channels x 4 fp16 per uint4 (25 MB)
__device__ int     g_deg[N_NODES];
__device__ int     g_rowptr[N_NODES + 1];
__device__ int     g_cursor[N_NODES];
__device__ int     g_csrc[N_EDGES];
__device__ uint2   g_coefh[N_EDGES];         // 4 x fp16 coef (8 MB)

// e3nn fan-in norms * 1/sqrt(2) * 1/sqrt(DEG=16)
#define K1C (0.03125f)
#define K2C (0.025515518f)
#define K3C (0.03125f)
#define K4C (0.044194174f)

__device__ __forceinline__ unsigned int h2u(float a, float b) {
    __half2 h = __floats2half2_rn(a, b);
    return *(const unsigned int*)&h;
}
__device__ __forceinline__ uint2 pack4h(float a, float b, float c, float d) {
    uint2 r; r.x = h2u(a, b); r.y = h2u(c, d); return r;
}
__device__ __forceinline__ float4 unpack4h(uint2 p) {
    float2 lo = __half22float2(*(const __half2*)&p.x);
    float2 hi = __half22float2(*(const __half2*)&p.y);
    return make_float4(lo.x, lo.y, hi.x, hi.y);
}
__device__ __forceinline__ float2 u2f2(unsigned int u) {
    return __half22float2(*(const __half2*)&u);
}

// ---------------- preprocessing ----------------
__global__ void k_zero(int* __restrict__ deg) {
    int i = blockIdx.x * blockDim.x + threadIdx.x;
    if (i < N_NODES) deg[i] = 0;
}

__global__ void k_hist(const int* __restrict__ dst, int* __restrict__ deg) {
    int e = blockIdx.x * blockDim.x + threadIdx.x;
    if (e < N_EDGES) atomicAdd(&deg[dst[e]], 1);
}

// single-block (1024 threads) exclusive scan over 65536 ints; each thread owns 64
__global__ __launch_bounds__(1024) void k_scan(
    const int* __restrict__ deg, int* __restrict__ rowptr, int* __restrict__ cursor)
{
    __shared__ int wsum[32];
    int tid = threadIdx.x;
    int lane = tid & 31, wid = tid >> 5;
    int base = tid * 64;
    const int4* d4 = (const int4*)(deg + base);
    int s = 0;
#pragma unroll
    for (int i = 0; i < 16; i++) {
        int4 v = d4[i];
        s += v.x + v.y + v.z + v.w;
    }
    int v = s;
#pragma unroll
    for (int d = 1; d < 32; d <<= 1) {
        int t = __shfl_up_sync(0xffffffffu, v, d);
        if (lane >= d) v += t;
    }
    if (lane == 31) wsum[wid] = v;
    __syncthreads();
    if (wid == 0) {
        int w = wsum[lane];
        int wv = w;
#pragma unroll
        for (int d = 1; d < 32; d <<= 1) {
            int t = __shfl_up_sync(0xffffffffu, wv, d);
            if (lane >= d) wv += t;
        }
        wsum[lane] = wv - w;
    }
    __syncthreads();
    int off = wsum[wid] + (v - s);
#pragma unroll
    for (int i = 0; i < 16; i++) {
        int4 dv = d4[i];
        int b = base + i * 4;
        rowptr[b + 0] = off; cursor[b + 0] = off; off += dv.x;
        rowptr[b + 1] = off; cursor[b + 1] = off; off += dv.y;
        rowptr[b + 2] = off; cursor[b + 2] = off; off += dv.z;
        rowptr[b + 3] = off; cursor[b + 3] = off; off += dv.w;
    }
    if (tid == 1023) rowptr[N_NODES] = off;
}

__global__ void k_csr(const int* __restrict__ src, const int* __restrict__ dst,
                      const float4* __restrict__ eattr,
                      int* __restrict__ cursor, int* __restrict__ csrc,
                      uint2* __restrict__ coefh) {
    int e = blockIdx.x * blockDim.x + threadIdx.x;
    if (e >= N_EDGES) return;
    int d = dst[e];
    int pos = atomicAdd(&cursor[d], 1);
    csrc[pos] = src[e];
    float4 cf = eattr[e];
    coefh[pos] = pack4h(cf.x, cf.y, cf.z, cf.w);   // (s2, v2x, v2y, v2z)
}

// ---------------- input embed: h = x @ W_in + b_in (fp16 out) ----------------
__global__ void k_input(const float* __restrict__ x, const float* __restrict__ W_in,
                        const float* __restrict__ b_in, __half2* __restrict__ hh) {
    int id = blockIdx.x * blockDim.x + threadIdx.x;   // N*40
    if (id >= N_NODES * 40) return;
    int n = id / 40, p = id % 40;
    int c0 = 2 * p, c1 = c0 + 1;
    const float* xr = x + n * 16;
    float a0 = b_in[c0], a1 = b_in[c1];
#pragma unroll
    for (int i = 0; i < 16; i++) {
        float xi = xr[i];
        a0 = fmaf(xi, W_in[i * HID + c0], a0);
        a1 = fmaf(xi, W_in[i * HID + c1], a1);
    }
    hh[id] = __floats2half2_rn(a0, a1);
}

// ---------------- per-node transform: register-blocked 2 nodes x 2 channels ----
__global__ __launch_bounds__(192) void k_node(
    const __half2* __restrict__ hh,
    const float* __restrict__ w1, const float* __restrict__ w2,
    const float* __restrict__ w3, const float* __restrict__ w4,
    uint4* __restrict__ Vq)
{
    __shared__ float s_w1[1024];   // 32x32, prescaled K1
    __shared__ float s_w2[512];    // 16x32, prescaled K2
    __shared__ float s_w3[512];    // 32x16, prescaled K3
    __shared__ float s_w4[256];    // 16x16, prescaled K4
    __shared__ float s_h[NPB][HID];
    int tid = threadIdx.x;
    for (int i = tid; i < 1024; i += 192) s_w1[i] = K1C * w1[i];
    for (int i = tid; i < 512;  i += 192) s_w2[i] = K2C * w2[i];
    for (int i = tid; i < 512;  i += 192) s_w3[i] = K3C * w3[i];
    for (int i = tid; i < 256;  i += 192) s_w4[i] = K4C * w4[i];
    int nb = blockIdx.x * NPB;
    {
        const uint2* h4 = (const uint2*)(hh + nb * 40);
        float4* sh4 = (float4*)&s_h[0][0];
        for (int i = tid; i < NPB * 20; i += 192) sh4[i] = unpack4h(h4[i]);
    }
    __syncthreads();

    int g  = tid / 24;   // node pair 0..7
    int cp = tid % 24;   // channel pair (0-15 scalar, 16-23 vector)
    const float* hA = s_h[2 * g];
    const float* hB = s_h[2 * g + 1];
    uint4* VA = Vq + (nb + 2 * g) * VPN;
    uint4* VB = VA + VPN;

    if (cp < 16) {
        int c0 = 2 * cp, c1 = c0 + 1;
        float pA0 = 0.f, pA1 = 0.f, pB0 = 0.f, pB1 = 0.f;
#pragma unroll
        for (int a = 0; a < 32; a++) {
            float xA = hA[a], xB = hB[a];
            float u = s_w1[a * 32 + c0], v = s_w1[a * 32 + c1];
            pA0 = fmaf(xA, u, pA0); pA1 = fmaf(xA, v, pA1);
            pB0 = fmaf(xB, u, pB0); pB1 = fmaf(xB, v, pB1);
        }
        float tA0x = 0.f, tA0y = 0.f, tA0z = 0.f;
        float tA1x = 0.f, tA1y = 0.f, tA1z = 0.f;
        float tB0x = 0.f, tB0y = 0.f, tB0z = 0.f;
        float tB1x = 0.f, tB1y = 0.f, tB1z = 0.f;
#pragma unroll
        for (int a = 0; a < 16; a++) {
            float u = s_w2[a * 32 + c0], v = s_w2[a * 32 + c1];
            float xA = hA[32 + a * 3], yA = hA[32 + a * 3 + 1], zA = hA[32 + a * 3 + 2];
            float xB = hB[32 + a * 3], yB = hB[32 + a * 3 + 1], zB = hB[32 + a * 3 + 2];
            tA0x = fmaf(xA, u, tA0x); tA0y = fmaf(yA, u, tA0y); tA0z = fmaf(zA, u, tA0z);
            tA1x = fmaf(xA, v, tA1x); tA1y = fmaf(yA, v, tA1y); tA1z = fmaf(zA, v, tA1z);
            tB0x = fmaf(xB, u, tB0x); tB0y = fmaf(yB, u, tB0y); tB0z = fmaf(zB, u, tB0z);
            tB1x = fmaf(xB, v, tB1x); tB1y = fmaf(yB, v, tB1y); tB1z = fmaf(zB, v, tB1z);
        }
        uint4 ra; ra.x = h2u(pA0, tA0x); ra.y = h2u(tA0y, tA0z);
                  ra.z = h2u(pA1, tA1x); ra.w = h2u(tA1y, tA1z);
        uint4 rb; rb.x = h2u(pB0, tB0x); rb.y = h2u(tB0y, tB0z);
                  rb.z = h2u(pB1, tB1x); rb.w = h2u(tB1y, tB1z);
        VA[cp] = ra;
        VB[cp] = rb;
    } else {
        int c0 = (cp - 16) * 2, c1 = c0 + 1;
        float pA0 = 0.f, pA1 = 0.f, pB0 = 0.f, pB1 = 0.f;
#pragma unroll
        for (int a = 0; a < 32; a++) {
            float xA = hA[a], xB = hB[a];
            float u = s_w3[a * 16 + c0], v = s_w3[a * 16 + c1];
            pA0 = fmaf(xA, u, pA0); pA1 = fmaf(xA, v, pA1);
            pB0 = fmaf(xB, u, pB0); pB1 = fmaf(xB, v, pB1);
        }
        float tA0x = 0.f, tA0y = 0.f, tA0z = 0.f;
        float tA1x = 0.f, tA1y = 0.f, tA1z = 0.f;
        float tB0x = 0.f, tB0y = 0.f, tB0z = 0.f;
        float tB1x = 0.f, tB1y = 0.f, tB1z = 0.f;
#pragma unroll
        for (int a = 0; a < 16; a++) {
            float u = s_w4[a * 16 + c0], v = s_w4[a * 16 + c1];
            float xA = hA[32 + a * 3], yA = hA[32 + a * 3 + 1], zA = hA[32 + a * 3 + 2];
            float xB = hB[32 + a * 3], yB = hB[32 + a * 3 + 1], zB = hB[32 + a * 3 + 2];
            tA0x = fmaf(xA, u, tA0x); tA0y = fmaf(yA, u, tA0y); tA0z = fmaf(zA, u, tA0z);
            tA1x = fmaf(xA, v, tA1x); tA1y = fmaf(yA, v, tA1y); tA1z = fmaf(zA, v, tA1z);
            tB0x = fmaf(xB, u, tB0x); tB0y = fmaf(yB, u, tB0y); tB0z = fmaf(zB, u, tB0z);
            tB1x = fmaf(xB, v, tB1x); tB1y = fmaf(yB, v, tB1y); tB1z = fmaf(zB, v, tB1z);
        }
        uint4 ra; ra.x = h2u(pA0, tA0x); ra.y = h2u(tA0y, tA0z);
                  ra.z = h2u(pA1, tA1x); ra.w = h2u(tA1y, tA1z);
        uint4 rb; rb.x = h2u(pB0, tB0x); rb.y = h2u(tB0y, tB0z);
                  rb.z = h2u(pB1, tB1x); rb.w = h2u(tB1y, tB1z);
        VA[cp] = ra;   // vector pairs live at indices 16..23
        VB[cp] = rb;
    }
}

// ---------------- aggregation: ONE WARP per dst node, no block sync ---------------
// lane < 16: scalar channel pair (2*lane, 2*lane+1) -> accums a0 (c0), b0 (c1)
// lane 16..23: vector channel pair -> accums a0,a1,a2 (c0) and b0,b1,b2 (c1)
__device__ __forceinline__ void agg_warp(
    const uint4* __restrict__ Vq, const int* __restrict__ rowptr,
    const int* __restrict__ csrc, const uint2* __restrict__ coefh,
    int n, int wid, int lane, int (*s_src)[32], float4 (*s_cf)[32],
    float& a0, float& a1, float& a2, float& b0, float& b1, float& b2)
{
    int beg = rowptr[n], end = rowptr[n + 1];
    a0 = a1 = a2 = b0 = b1 = b2 = 0.f;
    bool is_s = (lane < 16);
    for (int base = beg; base < end; base += 32) {
        int cnt = min(32, end - base);
        __syncwarp();
        if (lane < cnt) {
            s_src[wid][lane] = csrc[base + lane];
            s_cf[wid][lane]  = unpack4h(coefh[base + lane]);
        }
        __syncwarp();
        if (lane < VPN) {
#pragma unroll 4
            for (int i = 0; i < cnt; i++) {
                int s = s_src[wid][i];
                float4 cf = s_cf[wid][i];
                uint4 vp = Vq[s * VPN + lane];
                float2 p0 = u2f2(vp.x);   // (P0, tx0)
                float2 p1 = u2f2(vp.y);   // (ty0, tz0)
                float2 q0 = u2f2(vp.z);   // (P1, tx1)
                float2 q1 = u2f2(vp.w);   // (ty1, tz1)
                if (is_s) {
                    a0 = fmaf(cf.x, p0.x, a0); a0 = fmaf(cf.y, p0.y, a0);
                    a0 = fmaf(cf.z, p1.x, a0); a0 = fmaf(cf.w, p1.y, a0);
                    b0 = fmaf(cf.x, q0.x, b0); b0 = fmaf(cf.y, q0.y, b0);
                    b0 = fmaf(cf.z, q1.x, b0); b0 = fmaf(cf.w, q1.y, b0);
                } else {
                    a0 = fmaf(cf.y, p0.x, fmaf(cf.x, p0.y, a0));
                    a1 = fmaf(cf.z, p0.x, fmaf(cf.x, p1.x, a1));
                    a2 = fmaf(cf.w, p0.x, fmaf(cf.x, p1.y, a2));
                    b0 = fmaf(cf.y, q0.x, fmaf(cf.x, q0.y, b0));
                    b1 = fmaf(cf.z, q0.x, fmaf(cf.x, q1.x, b1));
                    b2 = fmaf(cf.w, q0.x, fmaf(cf.x, q1.y, b2));
                }
            }
        }
    }
}

__global__ __launch_bounds__(256) void k_agg(
    const uint4* __restrict__ Vq, const int* __restrict__ rowptr,
    const int* __restrict__ csrc, const uint2* __restrict__ coefh,
    __half2* __restrict__ hh)
{
    __shared__ int    s_src[8][32];
    __shared__ float4 s_cf[8][32];
    int wid = threadIdx.x >> 5, lane = threadIdx.x & 31;
    int n = blockIdx.x * 8 + wid;
    float a0, a1, a2, b0, b1, b2;
    agg_warp(Vq, rowptr, csrc, coefh, n, wid, lane, s_src, s_cf, a0, a1, a2, b0, b1, b2);
    if (lane < 16) {
        hh[n * 40 + lane] = __floats2half2_rn(a0, b0);
    } else if (lane < VPN) {
        int m = lane - 16;   // 6 contiguous floats at h[32+6m]
        __half2* o = hh + n * 40 + 16 + 3 * m;
        o[0] = __floats2half2_rn(a0, a1);
        o[1] = __floats2half2_rn(a2, b0);
        o[2] = __floats2half2_rn(b1, b2);
    }
}

// last layer: fuse ReLU + W_out readout, warp-local via smem
__global__ __launch_bounds__(256) void k_agg_final(
    const uint4* __restrict__ Vq, const int* __restrict__ rowptr,
    const int* __restrict__ csrc, const uint2* __restrict__ coefh,
    const float* __restrict__ W_out, const float* __restrict__ b_out,
    float* __restrict__ out)
{
    __shared__ int    s_src[8][32];
    __shared__ float4 s_cf[8][32];
    __shared__ float  s_o[8][HID];
    int wid = threadIdx.x >> 5, lane = threadIdx.x & 31;
    int n = blockIdx.x * 8 + wid;
    float a0, a1, a2, b0, b1, b2;
    agg_warp(Vq, rowptr, csrc, coefh, n, wid, lane, s_src, s_cf, a0, a1, a2, b0, b1, b2);
    __syncwarp();
    if (lane < 16) {
        s_o[wid][2 * lane]     = fmaxf(a0, 0.f);
        s_o[wid][2 * lane + 1] = fmaxf(b0, 0.f);
    } else if (lane < VPN) {
        int m = lane - 16;
        float* o = &s_o[wid][32 + 6 * m];
        o[0] = fmaxf(a0, 0.f); o[1] = fmaxf(a1, 0.f); o[2] = fmaxf(a2, 0.f);
        o[3] = fmaxf(b0, 0.f); o[4] = fmaxf(b1, 0.f); o[5] = fmaxf(b2, 0.f);
    }
    __syncwarp();
    if (lane < 8) {
        float acc = b_out[lane];
        const float* so = s_o[wid];
#pragma unroll
        for (int c = 0; c < HID; c++)
            acc = fmaf(so[c], W_out[c * 8 + lane], acc);
        out[n * 8 + lane] = acc;
    }
}

// ---------------- launch ----------------
extern "C" void kernel_launch(void* const* d_in, const int* in_sizes, int n_in,
                              void* d_out, int out_size) {
    const float* x     = (const float*)d_in[0];
    const int*   eidx  = (const int*)d_in[1];     // (2, E) int32: row0=src, row1=dst
    const float* eattr = (const float*)d_in[2];   // (E, 4)
    const float* W_in  = (const float*)d_in[3];
    const float* b_in  = (const float*)d_in[4];
    const float* tpw1  = (const float*)d_in[5];   // (3,32,32)
    const float* tpw2  = (const float*)d_in[6];   // (3,16,32)
    const float* tpw3  = (const float*)d_in[7];   // (3,32,16)
    const float* tpw4  = (const float*)d_in[8];   // (3,16,16)
    const float* W_out = (const float*)d_in[9];
    const float* b_out = (const float*)d_in[10];
    float* out = (float*)d_out;

    __half2 *hh; uint4 *Vq; uint2 *coefh; int *deg, *rowptr, *cursor, *csrc;
    cudaGetSymbolAddress((void**)&hh,     g_hh);
    cudaGetSymbolAddress((void**)&Vq,     g_V);
    cudaGetSymbolAddress((void**)&deg,    g_deg);
    cudaGetSymbolAddress((void**)&rowptr, g_rowptr);
    cudaGetSymbolAddress((void**)&cursor, g_cursor);
    cudaGetSymbolAddress((void**)&csrc,   g_csrc);
    cudaGetSymbolAddress((void**)&coefh,  g_coefh);

    const int* src = eidx;
    const int* dst = eidx + N_EDGES;

    // CSR build
    k_zero<<<N_NODES / 256, 256>>>(deg);
    k_hist<<<N_EDGES / 256, 256>>>(dst, deg);
    k_scan<<<1, 1024>>>(deg, rowptr, cursor);
    k_csr<<<N_EDGES / 256, 256>>>(src, dst, (const float4*)eattr, cursor, csrc, coefh);

    // input embed (fp16 h)
    k_input<<<(N_NODES * 40) / 256, 256>>>(x, W_in, b_in, hh);

    // layers 0,1: node transform + aggregate (h updated in place; k_agg never reads h)
    for (int l = 0; l < 2; l++) {
        k_node<<<N_NODES / NPB, 192>>>(hh,
            tpw1 + l * 32 * 32, tpw2 + l * 16 * 32,
            tpw3 + l * 32 * 16, tpw4 + l * 16 * 16, Vq);
        k_agg<<<N_NODES / 8, 256>>>(Vq, rowptr, csrc, coefh, hh);
    }

    // layer 2 fused with readout
    k_node<<<N_NODES / NPB, 192>>>(hh,
        tpw1 + 2 * 32 * 32, tpw2 + 2 * 16 * 32,
        tpw3 + 2 * 32 * 16, tpw4 + 2 * 16 * 16, Vq);
    k_agg_final<<<N_NODES / 8, 256>>>(Vq, rowptr, csrc, coefh, W_out, b_out, out);
}